// round 7
// baseline (speedup 1.0000x reference)
#include <cuda_runtime.h>
#include <cuda_bf16.h>
#include <cstdint>

#define N_SVC  50000
#define N_INST 100000
#define N_NODE 50000
#define HDIM   128
#define ODIM   256
#define NTOT   200000
#define NKT    12544
#define NTILE_VALID 12500
#define GCHUNK 112
#define KT_PER_CHUNK 112

#define E_SC 400000
#define E_IN 100000
#define E_NI 100000
#define E_II 800000
#define E_TOT 1400000

#define NDST 300000
#define SCAN_BLKS 293

// ---------------- scratch ----------------
__device__ float g_hsc[(size_t)N_SVC * HDIM];
__device__ float g_hin[(size_t)N_INST * HDIM];
__device__ float g_hni[(size_t)N_NODE * HDIM];
__device__ float g_hii[(size_t)N_INST * HDIM];
__device__ float g_deg[600000];
__device__ int   g_cnt[600000];
__device__ int   g_off[NDST + 1];      // +1 sentinel = E_TOT
__device__ int   g_cur[NDST];
__device__ int   g_bsum[SCAN_BLKS + 1];
__device__ int   g_elist[E_TOT];
__device__ uint2 g_bth[(size_t)NKT * 512];
__device__ uint2 g_btl[(size_t)NKT * 512];
__device__ uint2 g_wfr[4][2][4096];

#define OFF_NS_SC 0
#define OFF_ND_SC 50000
#define OFF_NS_IN 100000
#define OFF_ND_IN 200000
#define OFF_NS_NI 250000
#define OFF_ND_NI 300000
#define OFF_NS_II 400000
#define OFF_ND_II 500000
// concatenated dst space: SVC [0,50k) NODE [50k,100k) NI [100k,200k) II [200k,300k)

__device__ __forceinline__ int dmap(int i) {
    if (i < 50000)  return OFF_ND_SC + i;
    if (i < 100000) return OFF_ND_IN + (i - 50000);
    if (i < 200000) return OFF_ND_NI + (i - 100000);
    return OFF_ND_II + (i - 200000);
}

// ---------------- helpers ----------------
__device__ __forceinline__ void cvt_hilo(float x, float y, uint32_t& hi, uint32_t& lo) {
    __nv_bfloat16 hx = __float2bfloat16(x), hy = __float2bfloat16(y);
    float rx = x - __bfloat162float(hx), ry = y - __bfloat162float(hy);
    __nv_bfloat16 lx = __float2bfloat16(rx), ly = __float2bfloat16(ry);
    hi = (uint32_t)__bfloat16_as_ushort(hx) | ((uint32_t)__bfloat16_as_ushort(hy) << 16);
    lo = (uint32_t)__bfloat16_as_ushort(lx) | ((uint32_t)__bfloat16_as_ushort(ly) << 16);
}

__device__ __forceinline__ void mma16816(float* c, const uint32_t* a, uint32_t b0, uint32_t b1) {
    asm volatile(
        "mma.sync.aligned.m16n8k16.row.col.f32.bf16.bf16.f32 "
        "{%0,%1,%2,%3}, {%4,%5,%6,%7}, {%8,%9}, {%0,%1,%2,%3};"
        : "+f"(c[0]), "+f"(c[1]), "+f"(c[2]), "+f"(c[3])
        : "r"(a[0]), "r"(a[1]), "r"(a[2]), "r"(a[3]), "r"(b0), "r"(b1));
}

// ---------------- graph prep ----------------
__global__ void k_zeroi(int* __restrict__ p, int n) {
    int i = blockIdx.x * blockDim.x + threadIdx.x;
    if (i < n) p[i] = 0;
}

__global__ void k_count(const int* __restrict__ svc_src, const int* __restrict__ svc_dst,
                        const int* __restrict__ in_src, const int* __restrict__ in_dst,
                        const int* __restrict__ ni_src, const int* __restrict__ ni_dst,
                        const int* __restrict__ ii_src, const int* __restrict__ ii_dst,
                        int* __restrict__ cnt) {
    int i = blockIdx.x * blockDim.x + threadIdx.x;
    const int* p; int off, j;
    if      (i <  400000) { p = svc_src; off = OFF_NS_SC; j = i; }
    else if (i <  800000) { p = svc_dst; off = OFF_ND_SC; j = i - 400000; }
    else if (i <  900000) { p = in_src;  off = OFF_NS_IN; j = i - 800000; }
    else if (i < 1000000) { p = in_dst;  off = OFF_ND_IN; j = i - 900000; }
    else if (i < 1100000) { p = ni_src;  off = OFF_NS_NI; j = i - 1000000; }
    else if (i < 1200000) { p = ni_dst;  off = OFF_ND_NI; j = i - 1100000; }
    else if (i < 2000000) { p = ii_src;  off = OFF_NS_II; j = i - 1200000; }
    else if (i < 2800000) { p = ii_dst;  off = OFF_ND_II; j = i - 2000000; }
    else return;
    atomicAdd(&cnt[off + __ldg(&p[j])], 1);
}

__global__ void k_norm(const int* __restrict__ cnt, float* __restrict__ deg, int n) {
    int i = blockIdx.x * blockDim.x + threadIdx.x;
    if (i < n) deg[i] = rsqrtf(fmaxf((float)cnt[i], 1.0f));
}

__global__ __launch_bounds__(1024) void k_scanA(const int* __restrict__ cnt,
                                                int* __restrict__ off,
                                                int* __restrict__ bsum) {
    __shared__ int wsum[32];
    int i = blockIdx.x * 1024 + threadIdx.x;
    int lane = threadIdx.x & 31, wid = threadIdx.x >> 5;
    int v = (i < NDST) ? cnt[dmap(i)] : 0;
    int s = v;
#pragma unroll
    for (int d = 1; d < 32; d <<= 1) {
        int t = __shfl_up_sync(0xFFFFFFFFu, s, d);
        if (lane >= d) s += t;
    }
    if (lane == 31) wsum[wid] = s;
    __syncthreads();
    if (wid == 0) {
        int w = wsum[lane];
        int ws = w;
#pragma unroll
        for (int d = 1; d < 32; d <<= 1) {
            int t = __shfl_up_sync(0xFFFFFFFFu, ws, d);
            if (lane >= d) ws += t;
        }
        wsum[lane] = ws - w;
        if (lane == 31) bsum[blockIdx.x] = ws;
    }
    __syncthreads();
    if (i < NDST) off[i] = s - v + wsum[wid];
}

__global__ __launch_bounds__(512) void k_scanB(int* __restrict__ bsum) {
    __shared__ int sh[512];
    int i = threadIdx.x;
    int v = (i < SCAN_BLKS) ? bsum[i] : 0;
    sh[i] = v;
    __syncthreads();
#pragma unroll
    for (int d = 1; d < 512; d <<= 1) {
        int t = (i >= d) ? sh[i - d] : 0;
        __syncthreads();
        sh[i] += t;
        __syncthreads();
    }
    if (i < SCAN_BLKS) bsum[i] = sh[i] - v;
}

__global__ __launch_bounds__(1024) void k_scanC(int* __restrict__ off, int* __restrict__ cur,
                                                const int* __restrict__ bsum) {
    int i = blockIdx.x * 1024 + threadIdx.x;
    if (i < NDST) {
        int o = off[i] + bsum[blockIdx.x];
        off[i] = o;
        cur[i] = o;
    }
    if (i == 0) off[NDST] = E_TOT;   // sentinel
}

__global__ void k_fill(const int* __restrict__ svc_src, const int* __restrict__ svc_dst,
                       const int* __restrict__ in_src, const int* __restrict__ in_dst,
                       const int* __restrict__ ni_src, const int* __restrict__ ni_dst,
                       const int* __restrict__ ii_src, const int* __restrict__ ii_dst,
                       int* __restrict__ cur, int* __restrict__ elist) {
    int i = blockIdx.x * blockDim.x + threadIdx.x;
    int d, s, cb;
    if      (i <  400000) { int j = i;          d = __ldg(&svc_dst[j]); s = __ldg(&svc_src[j]); cb = 0; }
    else if (i <  500000) { int j = i - 400000; d = __ldg(&in_dst[j]);  s = __ldg(&in_src[j]);  cb = 50000; }
    else if (i <  600000) { int j = i - 500000; d = __ldg(&ni_dst[j]);  s = __ldg(&ni_src[j]);  cb = 100000; }
    else if (i < 1400000) { int j = i - 600000; d = __ldg(&ii_dst[j]);  s = __ldg(&ii_src[j]);  cb = 200000; }
    else return;
    int p = atomicAdd(&cur[cb + d], 1);
    elist[p] = s;
}

// ---------------- W prep ----------------
__global__ void k_prepW(const float* __restrict__ W, uint2* __restrict__ whi,
                        uint2* __restrict__ wlo) {
    int id = blockIdx.x * blockDim.x + threadIdx.x;
    int katom = id >> 9, rest = id & 511;
    int natom = rest >> 5, lane = rest & 31;
    int g = lane >> 2, tig = lane & 3;
    int n = natom * 8 + g;
    int k0 = katom * 16 + 2 * tig;
    uint32_t h0, l0, h1, l1;
    cvt_hilo(W[(k0) * 128 + n], W[(k0 + 1) * 128 + n], h0, l0);
    cvt_hilo(W[(k0 + 8) * 128 + n], W[(k0 + 9) * 128 + n], h1, l1);
    whi[id] = make_uint2(h0, h1);
    wlo[id] = make_uint2(l0, l1);
}

// ---- projection ----
__global__ __launch_bounds__(256, 2) void k_proj_mma(
    const float* __restrict__ X, const uint2* __restrict__ whi,
    const uint2* __restrict__ wlo, const float* __restrict__ ns,
    float* __restrict__ Hout, int nrows)
{
    __shared__ uint2 s_wh[4096];
    __shared__ uint2 s_wl[4096];
    const int tid = threadIdx.x, wid = tid >> 5, lane = tid & 31;
    const int g = lane >> 2, tig = lane & 3;
    const int row0 = blockIdx.x * 128;

    {
        const uint4* sh = (const uint4*)whi;
        const uint4* sl = (const uint4*)wlo;
#pragma unroll
        for (int j = 0; j < 8; j++) {
            ((uint4*)s_wh)[tid + 256 * j] = sh[tid + 256 * j];
            ((uint4*)s_wl)[tid + 256 * j] = sl[tid + 256 * j];
        }
    }
    __syncthreads();

    const int r0 = row0 + wid * 16 + g;
    const int r1 = r0 + 8;
    const bool v0 = (r0 < nrows), v1 = (r1 < nrows);
    const float* p0 = X + (size_t)r0 * 128;
    const float* p1 = X + (size_t)r1 * 128;

    float acc[16][4];
#pragma unroll
    for (int na = 0; na < 16; na++)
#pragma unroll
        for (int q = 0; q < 4; q++) acc[na][q] = 0.f;

    const float2 z2 = make_float2(0.f, 0.f);
#pragma unroll 1
    for (int ka = 0; ka < 8; ka++) {
        uint32_t ah[4], al[4];
        int kk = ka * 16 + 2 * tig;
        float2 x00 = v0 ? *(const float2*)(p0 + kk) : z2;
        float2 x01 = v0 ? *(const float2*)(p0 + kk + 8) : z2;
        float2 x10 = v1 ? *(const float2*)(p1 + kk) : z2;
        float2 x11 = v1 ? *(const float2*)(p1 + kk + 8) : z2;
        cvt_hilo(x00.x, x00.y, ah[0], al[0]);
        cvt_hilo(x10.x, x10.y, ah[1], al[1]);
        cvt_hilo(x01.x, x01.y, ah[2], al[2]);
        cvt_hilo(x11.x, x11.y, ah[3], al[3]);
#pragma unroll
        for (int na = 0; na < 16; na++) {
            uint2 bh = s_wh[(ka * 16 + na) * 32 + lane];
            uint2 bl = s_wl[(ka * 16 + na) * 32 + lane];
            mma16816(acc[na], ah, bh.x, bh.y);
            mma16816(acc[na], al, bh.x, bh.y);
            mma16816(acc[na], ah, bl.x, bl.y);
        }
    }

    float s0 = v0 ? ns[r0] : 0.f;
    float s1 = v1 ? ns[r1] : 0.f;
#pragma unroll
    for (int na = 0; na < 16; na++) {
        int col = na * 8 + 2 * tig;
        if (v0) *(float2*)(Hout + (size_t)r0 * 128 + col) =
            make_float2(acc[na][0] * s0, acc[na][1] * s0);
        if (v1) *(float2*)(Hout + (size_t)r1 * 128 + col) =
            make_float2(acc[na][2] * s1, acc[na][3] * s1);
    }
}

// ---- load-balanced fused aggregate + bias + leakyrelu + fragment pack ----
// Block = one k16 tile (16 dst rows). 16 warps round-robin over the block's
// contiguous edge range; binary-search the row; accumulate via smem atomics.
__global__ __launch_bounds__(512) void k_aggpack(
    const float* __restrict__ bsc, const float* __restrict__ bin,
    const float* __restrict__ bni, const float* __restrict__ bii,
    uint2* __restrict__ bth, uint2* __restrict__ btl)
{
    __shared__ float sA[16][128];
    __shared__ float sB[16][128];
    __shared__ int roff[34];
    const int t = blockIdx.x;
    const int tid = threadIdx.x, wid = tid >> 5, lane = tid & 31;

    for (int i = tid; i < 2048; i += 512) { ((float*)sA)[i] = 0.f; ((float*)sB)[i] = 0.f; }

    int c0, dga, dgb = 0;
    const float *Ha, *Hb = nullptr;
    if (t < 3125)      { int l = t * 16;          c0 = l;          Ha = g_hsc; dga = OFF_ND_SC + l; }
    else if (t < 6250) { int l = (t - 3125) * 16; c0 = 50000 + l;  Ha = g_hin; dga = OFF_ND_IN + l; }
    else               { int l = (t - 6250) * 16; c0 = 100000 + l; Ha = g_hni; dga = OFF_ND_NI + l;
                         Hb = g_hii; dgb = OFF_ND_II + l; }

    if (tid < 17) roff[tid] = g_off[c0 + tid];
    if (Hb && tid >= 32 && tid < 49) roff[17 + (tid - 32)] = g_off[c0 + 100000 + (tid - 32)];
    __syncthreads();

    // range A
    {
        int e1 = roff[16];
        for (int e = roff[0] + wid; e < e1; e += 16) {
            int r = 0;
#pragma unroll
            for (int stp = 8; stp; stp >>= 1)
                if (roff[r + stp] <= e) r += stp;
            int s = __ldg(&g_elist[e]);
            float4 v = *(const float4*)(Ha + (size_t)s * 128 + lane * 4);
            atomicAdd(&sA[r][lane * 4 + 0], v.x);
            atomicAdd(&sA[r][lane * 4 + 1], v.y);
            atomicAdd(&sA[r][lane * 4 + 2], v.z);
            atomicAdd(&sA[r][lane * 4 + 3], v.w);
        }
    }
    // range B (INST only)
    if (Hb) {
        int e1 = roff[33];
        for (int e = roff[17] + wid; e < e1; e += 16) {
            int r = 0;
#pragma unroll
            for (int stp = 8; stp; stp >>= 1)
                if (roff[17 + r + stp] <= e) r += stp;
            int s = __ldg(&g_elist[e]);
            float4 v = *(const float4*)(Hb + (size_t)s * 128 + lane * 4);
            atomicAdd(&sB[r][lane * 4 + 0], v.x);
            atomicAdd(&sB[r][lane * 4 + 1], v.y);
            atomicAdd(&sB[r][lane * 4 + 2], v.z);
            atomicAdd(&sB[r][lane * 4 + 3], v.w);
        }
    }
    __syncthreads();

    // combine: warp w owns row w
    {
        float n1 = g_deg[dga + wid];
        float n2 = Hb ? g_deg[dgb + wid] : 0.f;
        float b0, b1, b2, b3;
        if (t < 3125) {
            b0 = __ldg(&bsc[lane * 4]);     b1 = __ldg(&bsc[lane * 4 + 1]);
            b2 = __ldg(&bsc[lane * 4 + 2]); b3 = __ldg(&bsc[lane * 4 + 3]);
        } else if (t < 6250) {
            b0 = __ldg(&bin[lane * 4]);     b1 = __ldg(&bin[lane * 4 + 1]);
            b2 = __ldg(&bin[lane * 4 + 2]); b3 = __ldg(&bin[lane * 4 + 3]);
        } else {
            b0 = __ldg(&bni[lane * 4])     + __ldg(&bii[lane * 4]);
            b1 = __ldg(&bni[lane * 4 + 1]) + __ldg(&bii[lane * 4 + 1]);
            b2 = __ldg(&bni[lane * 4 + 2]) + __ldg(&bii[lane * 4 + 2]);
            b3 = __ldg(&bni[lane * 4 + 3]) + __ldg(&bii[lane * 4 + 3]);
        }
        float4 a = *(float4*)&sA[wid][lane * 4];
        float4 b = *(float4*)&sB[wid][lane * 4];
        float4 val = make_float4(a.x * n1 + b.x * n2 + b0, a.y * n1 + b.y * n2 + b1,
                                 a.z * n1 + b.z * n2 + b2, a.w * n1 + b.w * n2 + b3);
        val.x = (val.x >= 0.f) ? val.x : 0.01f * val.x;
        val.y = (val.y >= 0.f) ? val.y : 0.01f * val.y;
        val.z = (val.z >= 0.f) ? val.z : 0.01f * val.z;
        val.w = (val.w >= 0.f) ? val.w : 0.01f * val.w;
        *(float4*)&sA[wid][lane * 4] = val;
    }
    __syncthreads();

    if (tid < 128) {
        int h = tid;
#pragma unroll
        for (int j = 0; j < 4; j++) {
            int id = h + 128 * j;
            int lane2 = id & 31;
            int natom = id >> 5;
            int gg = lane2 >> 2, tig = lane2 & 3;
            int n = natom * 8 + gg;
            uint32_t h0, l0, h1, l1;
            cvt_hilo(sA[2 * tig][n], sA[2 * tig + 1][n], h0, l0);
            cvt_hilo(sA[2 * tig + 8][n], sA[2 * tig + 9][n], h1, l1);
            size_t o = (size_t)t * 512 + id;
            bth[o] = make_uint2(h0, h1);
            btl[o] = make_uint2(l0, l1);
        }
    }
}

__global__ void k_init_out(float* __restrict__ out, const float* __restrict__ btot) {
    int i = blockIdx.x * blockDim.x + threadIdx.x;
    if (i < ODIM * HDIM) out[i] = btot[i >> 7];
}

// ---- final GEMM ----
__global__ __launch_bounds__(256, 2) void k_gemm_mma(const float* __restrict__ Wt,
                                                     const uint2* __restrict__ bth,
                                                     const uint2* __restrict__ btl,
                                                     float* __restrict__ out) {
    __shared__ uint2 s_bh[4096];
    __shared__ uint2 s_bl[4096];
    const int tid = threadIdx.x, wid = tid >> 5, lane = tid & 31;
    const int g = lane >> 2, tig = lane & 3;
    const int chunk = blockIdx.x, mblk = blockIdx.y;

    const int r0 = mblk * 128 + wid * 16 + g;
    const int r1 = r0 + 8;
    const float* p0 = Wt + (size_t)r0 * NTOT;
    const float* p1 = Wt + (size_t)r1 * NTOT;

    float acc[16][4];
#pragma unroll
    for (int na = 0; na < 16; na++)
#pragma unroll
        for (int q = 0; q < 4; q++) acc[na][q] = 0.f;

    for (int sit = 0; sit < KT_PER_CHUNK / 8; sit++) {
        int tile0 = chunk * KT_PER_CHUNK + sit * 8;
        __syncthreads();
        {
            const uint4* sh = (const uint4*)(bth + (size_t)tile0 * 512);
            const uint4* sl = (const uint4*)(btl + (size_t)tile0 * 512);
#pragma unroll
            for (int j = 0; j < 8; j++) {
                ((uint4*)s_bh)[tid + 256 * j] = sh[tid + 256 * j];
                ((uint4*)s_bl)[tid + 256 * j] = sl[tid + 256 * j];
            }
        }
        __syncthreads();
        if (tile0 >= NTILE_VALID) continue;
#pragma unroll 1
        for (int kt = 0; kt < 8; kt++) {
            int ktg = tile0 + kt;
            if (ktg >= NTILE_VALID) break;
            uint32_t ah[4], al[4];
            size_t kk = (size_t)ktg * 16 + 2 * tig;
            float2 x00 = *(const float2*)(p0 + kk);
            float2 x01 = *(const float2*)(p0 + kk + 8);
            float2 x10 = *(const float2*)(p1 + kk);
            float2 x11 = *(const float2*)(p1 + kk + 8);
            cvt_hilo(x00.x, x00.y, ah[0], al[0]);
            cvt_hilo(x10.x, x10.y, ah[1], al[1]);
            cvt_hilo(x01.x, x01.y, ah[2], al[2]);
            cvt_hilo(x11.x, x11.y, ah[3], al[3]);
#pragma unroll
            for (int na = 0; na < 16; na++) {
                uint2 bh = s_bh[(kt * 16 + na) * 32 + lane];
                uint2 bl = s_bl[(kt * 16 + na) * 32 + lane];
                mma16816(acc[na], ah, bh.x, bh.y);
                mma16816(acc[na], al, bh.x, bh.y);
                mma16816(acc[na], ah, bl.x, bl.y);
            }
        }
    }

#pragma unroll
    for (int na = 0; na < 16; na++) {
        int col = na * 8 + 2 * tig;
        float* d0 = out + (size_t)r0 * 128 + col;
        float* d1 = out + (size_t)r1 * 128 + col;
        asm volatile("red.global.add.v2.f32 [%0], {%1, %2};"
                     :: "l"(d0), "f"(acc[na][0]), "f"(acc[na][1]) : "memory");
        asm volatile("red.global.add.v2.f32 [%0], {%1, %2};"
                     :: "l"(d1), "f"(acc[na][2]), "f"(acc[na][3]) : "memory");
    }
}

// ---------------- host ----------------
extern "C" void kernel_launch(void* const* d_in, const int* in_sizes, int n_in,
                              void* d_out, int out_size) {
    (void)in_sizes; (void)n_in; (void)out_size;
    const float* feat_svc  = (const float*)d_in[0];
    const float* feat_inst = (const float*)d_in[1];
    const float* feat_node = (const float*)d_in[2];
    const int* svc_src = (const int*)d_in[3];
    const int* svc_dst = (const int*)d_in[4];
    const int* in_src  = (const int*)d_in[5];
    const int* in_dst  = (const int*)d_in[6];
    const int* ni_src  = (const int*)d_in[7];
    const int* ni_dst  = (const int*)d_in[8];
    const int* ii_src  = (const int*)d_in[9];
    const int* ii_dst  = (const int*)d_in[10];
    const float* W_sc = (const float*)d_in[11];
    const float* b_sc = (const float*)d_in[12];
    const float* W_in = (const float*)d_in[13];
    const float* b_in = (const float*)d_in[14];
    const float* W_ni = (const float*)d_in[15];
    const float* b_ni = (const float*)d_in[16];
    const float* W_ii = (const float*)d_in[17];
    const float* b_ii = (const float*)d_in[18];
    const float* W_tot = (const float*)d_in[19];
    const float* b_tot = (const float*)d_in[20];
    float* out = (float*)d_out;

    float *p_hsc, *p_hin, *p_hni, *p_hii, *p_deg;
    int *p_cnt, *p_off, *p_cur, *p_el, *p_bsum;
    uint2 *p_bth, *p_btl, *p_wfr;
    cudaGetSymbolAddress((void**)&p_hsc, g_hsc);
    cudaGetSymbolAddress((void**)&p_hin, g_hin);
    cudaGetSymbolAddress((void**)&p_hni, g_hni);
    cudaGetSymbolAddress((void**)&p_hii, g_hii);
    cudaGetSymbolAddress((void**)&p_deg, g_deg);
    cudaGetSymbolAddress((void**)&p_cnt, g_cnt);
    cudaGetSymbolAddress((void**)&p_off, g_off);
    cudaGetSymbolAddress((void**)&p_cur, g_cur);
    cudaGetSymbolAddress((void**)&p_el,  g_elist);
    cudaGetSymbolAddress((void**)&p_bsum, g_bsum);
    cudaGetSymbolAddress((void**)&p_bth, g_bth);
    cudaGetSymbolAddress((void**)&p_btl, g_btl);
    cudaGetSymbolAddress((void**)&p_wfr, g_wfr);

    // streams/events created on first (non-captured) correctness call, reused after
    static cudaStream_t s1 = nullptr, s2 = nullptr;
    static cudaEvent_t evRoot = nullptr, evCount = nullptr, evPrep = nullptr, evFill = nullptr;
    if (s1 == nullptr) {
        cudaStreamCreateWithFlags(&s1, cudaStreamNonBlocking);
        cudaStreamCreateWithFlags(&s2, cudaStreamNonBlocking);
        cudaEventCreateWithFlags(&evRoot, cudaEventDisableTiming);
        cudaEventCreateWithFlags(&evCount, cudaEventDisableTiming);
        cudaEventCreateWithFlags(&evPrep, cudaEventDisableTiming);
        cudaEventCreateWithFlags(&evFill, cudaEventDisableTiming);
    }

    // fork root
    cudaEventRecord(evRoot, 0);

    // s2 branch: W fragment prep + output init (independent of everything)
    cudaStreamWaitEvent(s2, evRoot, 0);
    k_prepW<<<16, 256, 0, s2>>>(W_sc, p_wfr + 0 * 8192, p_wfr + 0 * 8192 + 4096);
    k_prepW<<<16, 256, 0, s2>>>(W_in, p_wfr + 1 * 8192, p_wfr + 1 * 8192 + 4096);
    k_prepW<<<16, 256, 0, s2>>>(W_ni, p_wfr + 2 * 8192, p_wfr + 2 * 8192 + 4096);
    k_prepW<<<16, 256, 0, s2>>>(W_ii, p_wfr + 3 * 8192, p_wfr + 3 * 8192 + 4096);
    k_init_out<<<(ODIM * HDIM + 255) / 256, 256, 0, s2>>>(out, b_tot);
    cudaEventRecord(evPrep, s2);

    // default: counts + norms
    k_zeroi<<<(600000 + 255) / 256, 256>>>(p_cnt, 600000);
    k_count<<<(2800000 + 255) / 256, 256>>>(svc_src, svc_dst, in_src, in_dst,
                                            ni_src, ni_dst, ii_src, ii_dst, p_cnt);
    cudaEventRecord(evCount, 0);
    k_norm<<<(600000 + 255) / 256, 256>>>(p_cnt, p_deg, 600000);

    // s1 branch: CSR build (needs counts only)
    cudaStreamWaitEvent(s1, evCount, 0);
    k_scanA<<<SCAN_BLKS, 1024, 0, s1>>>(p_cnt, p_off, p_bsum);
    k_scanB<<<1, 512, 0, s1>>>(p_bsum);
    k_scanC<<<SCAN_BLKS, 1024, 0, s1>>>(p_off, p_cur, p_bsum);
    k_fill<<<(E_TOT + 255) / 256, 256, 0, s1>>>(svc_src, svc_dst, in_src, in_dst,
                                                ni_src, ni_dst, ii_src, ii_dst, p_cur, p_el);
    cudaEventRecord(evFill, s1);

    // default: projections (need norms + W fragments)
    cudaStreamWaitEvent(0, evPrep, 0);
    k_proj_mma<<<(N_SVC  + 127) / 128, 256>>>(feat_svc,  p_wfr + 0 * 8192, p_wfr + 0 * 8192 + 4096, p_deg + OFF_NS_SC, p_hsc, N_SVC);
    k_proj_mma<<<(N_INST + 127) / 128, 256>>>(feat_inst, p_wfr + 1 * 8192, p_wfr + 1 * 8192 + 4096, p_deg + OFF_NS_IN, p_hin, N_INST);
    k_proj_mma<<<(N_NODE + 127) / 128, 256>>>(feat_node, p_wfr + 2 * 8192, p_wfr + 2 * 8192 + 4096, p_deg + OFF_NS_NI, p_hni, N_NODE);
    k_proj_mma<<<(N_INST + 127) / 128, 256>>>(feat_inst, p_wfr + 3 * 8192, p_wfr + 3 * 8192 + 4096, p_deg + OFF_NS_II, p_hii, N_INST);

    // join CSR branch, then aggregate + pack, then GEMM
    cudaStreamWaitEvent(0, evFill, 0);
    k_aggpack<<<NTILE_VALID, 512>>>(b_sc, b_in, b_ni, b_ii, p_bth, p_btl);

    dim3 gg(GCHUNK, 2);
    k_gemm_mma<<<gg, 256>>>(W_tot, p_bth, p_btl, out);
}

// round 8
// speedup vs baseline: 1.5710x; 1.5710x over previous
#include <cuda_runtime.h>
#include <cuda_bf16.h>
#include <cstdint>

#define N_SVC  50000
#define N_INST 100000
#define N_NODE 50000
#define HDIM   128
#define ODIM   256
#define NTOT   200000
#define NKT    12544
#define NTILE_VALID 12500
#define GCHUNK 112
#define KT_PER_CHUNK 112

#define E_SC 400000
#define E_IN 100000
#define E_NI 100000
#define E_II 800000
#define E_TOT 1400000

#define NDST 300000
#define SCAN_BLKS 293

// ---------------- scratch ----------------
__device__ float g_hsc[(size_t)N_SVC * HDIM];
__device__ float g_hin[(size_t)N_INST * HDIM];
__device__ float g_hni[(size_t)N_NODE * HDIM];
__device__ float g_hii[(size_t)N_INST * HDIM];
__device__ float g_deg[600000];
__device__ int   g_cnt[600000];
__device__ int   g_off[NDST + 1];
__device__ int   g_cur[NDST];
__device__ int   g_bsum[SCAN_BLKS + 1];
__device__ int   g_elist[E_TOT];
__device__ uint2 g_bth[(size_t)NKT * 512];
__device__ uint2 g_btl[(size_t)NKT * 512];
__device__ uint2 g_wfr[4][2][4096];

#define OFF_NS_SC 0
#define OFF_ND_SC 50000
#define OFF_NS_IN 100000
#define OFF_ND_IN 200000
#define OFF_NS_NI 250000
#define OFF_ND_NI 300000
#define OFF_NS_II 400000
#define OFF_ND_II 500000
// concatenated dst space bases (into g_off/g_cur)
#define OB_SC 0
#define OB_IN 50000
#define OB_NI 100000
#define OB_II 200000

__device__ __forceinline__ int dmap(int i) {
    if (i < 50000)  return OFF_ND_SC + i;
    if (i < 100000) return OFF_ND_IN + (i - 50000);
    if (i < 200000) return OFF_ND_NI + (i - 100000);
    return OFF_ND_II + (i - 200000);
}

// ---------------- helpers ----------------
__device__ __forceinline__ void cvt_hilo(float x, float y, uint32_t& hi, uint32_t& lo) {
    __nv_bfloat16 hx = __float2bfloat16(x), hy = __float2bfloat16(y);
    float rx = x - __bfloat162float(hx), ry = y - __bfloat162float(hy);
    __nv_bfloat16 lx = __float2bfloat16(rx), ly = __float2bfloat16(ry);
    hi = (uint32_t)__bfloat16_as_ushort(hx) | ((uint32_t)__bfloat16_as_ushort(hy) << 16);
    lo = (uint32_t)__bfloat16_as_ushort(lx) | ((uint32_t)__bfloat16_as_ushort(ly) << 16);
}

__device__ __forceinline__ void mma16816(float* c, const uint32_t* a, uint32_t b0, uint32_t b1) {
    asm volatile(
        "mma.sync.aligned.m16n8k16.row.col.f32.bf16.bf16.f32 "
        "{%0,%1,%2,%3}, {%4,%5,%6,%7}, {%8,%9}, {%0,%1,%2,%3};"
        : "+f"(c[0]), "+f"(c[1]), "+f"(c[2]), "+f"(c[3])
        : "r"(a[0]), "r"(a[1]), "r"(a[2]), "r"(a[3]), "r"(b0), "r"(b1));
}

// ---------------- graph prep ----------------
__global__ void k_zeroi(int* __restrict__ p, int n) {
    int i = blockIdx.x * blockDim.x + threadIdx.x;
    if (i < n) p[i] = 0;
}

__global__ void k_count(const int* __restrict__ svc_src, const int* __restrict__ svc_dst,
                        const int* __restrict__ in_src, const int* __restrict__ in_dst,
                        const int* __restrict__ ni_src, const int* __restrict__ ni_dst,
                        const int* __restrict__ ii_src, const int* __restrict__ ii_dst,
                        int* __restrict__ cnt) {
    int i = blockIdx.x * blockDim.x + threadIdx.x;
    const int* p; int off, j;
    if      (i <  400000) { p = svc_src; off = OFF_NS_SC; j = i; }
    else if (i <  800000) { p = svc_dst; off = OFF_ND_SC; j = i - 400000; }
    else if (i <  900000) { p = in_src;  off = OFF_NS_IN; j = i - 800000; }
    else if (i < 1000000) { p = in_dst;  off = OFF_ND_IN; j = i - 900000; }
    else if (i < 1100000) { p = ni_src;  off = OFF_NS_NI; j = i - 1000000; }
    else if (i < 1200000) { p = ni_dst;  off = OFF_ND_NI; j = i - 1100000; }
    else if (i < 2000000) { p = ii_src;  off = OFF_NS_II; j = i - 1200000; }
    else if (i < 2800000) { p = ii_dst;  off = OFF_ND_II; j = i - 2000000; }
    else return;
    atomicAdd(&cnt[off + __ldg(&p[j])], 1);
}

__global__ void k_norm(const int* __restrict__ cnt, float* __restrict__ deg, int n) {
    int i = blockIdx.x * blockDim.x + threadIdx.x;
    if (i < n) deg[i] = rsqrtf(fmaxf((float)cnt[i], 1.0f));
}

__global__ __launch_bounds__(1024) void k_scanA(const int* __restrict__ cnt,
                                                int* __restrict__ off,
                                                int* __restrict__ bsum) {
    __shared__ int wsum[32];
    int i = blockIdx.x * 1024 + threadIdx.x;
    int lane = threadIdx.x & 31, wid = threadIdx.x >> 5;
    int v = (i < NDST) ? cnt[dmap(i)] : 0;
    int s = v;
#pragma unroll
    for (int d = 1; d < 32; d <<= 1) {
        int t = __shfl_up_sync(0xFFFFFFFFu, s, d);
        if (lane >= d) s += t;
    }
    if (lane == 31) wsum[wid] = s;
    __syncthreads();
    if (wid == 0) {
        int w = wsum[lane];
        int ws = w;
#pragma unroll
        for (int d = 1; d < 32; d <<= 1) {
            int t = __shfl_up_sync(0xFFFFFFFFu, ws, d);
            if (lane >= d) ws += t;
        }
        wsum[lane] = ws - w;
        if (lane == 31) bsum[blockIdx.x] = ws;
    }
    __syncthreads();
    if (i < NDST) off[i] = s - v + wsum[wid];
}

__global__ __launch_bounds__(512) void k_scanB(int* __restrict__ bsum) {
    __shared__ int sh[512];
    int i = threadIdx.x;
    int v = (i < SCAN_BLKS) ? bsum[i] : 0;
    sh[i] = v;
    __syncthreads();
#pragma unroll
    for (int d = 1; d < 512; d <<= 1) {
        int t = (i >= d) ? sh[i - d] : 0;
        __syncthreads();
        sh[i] += t;
        __syncthreads();
    }
    if (i < SCAN_BLKS) bsum[i] = sh[i] - v;
}

__global__ __launch_bounds__(1024) void k_scanC(int* __restrict__ off, int* __restrict__ cur,
                                                const int* __restrict__ bsum) {
    int i = blockIdx.x * 1024 + threadIdx.x;
    if (i < NDST) {
        int o = off[i] + bsum[blockIdx.x];
        off[i] = o;
        cur[i] = o;
    }
    if (i == 0) off[NDST] = E_TOT;
}

__global__ void k_fill(const int* __restrict__ svc_src, const int* __restrict__ svc_dst,
                       const int* __restrict__ in_src, const int* __restrict__ in_dst,
                       const int* __restrict__ ni_src, const int* __restrict__ ni_dst,
                       const int* __restrict__ ii_src, const int* __restrict__ ii_dst,
                       int* __restrict__ cur, int* __restrict__ elist) {
    int i = blockIdx.x * blockDim.x + threadIdx.x;
    int d, s, cb;
    if      (i <  400000) { int j = i;          d = __ldg(&svc_dst[j]); s = __ldg(&svc_src[j]); cb = OB_SC; }
    else if (i <  500000) { int j = i - 400000; d = __ldg(&in_dst[j]);  s = __ldg(&in_src[j]);  cb = OB_IN; }
    else if (i <  600000) { int j = i - 500000; d = __ldg(&ni_dst[j]);  s = __ldg(&ni_src[j]);  cb = OB_NI; }
    else if (i < 1400000) { int j = i - 600000; d = __ldg(&ii_dst[j]);  s = __ldg(&ii_src[j]);  cb = OB_II; }
    else return;
    int p = atomicAdd(&cur[cb + d], 1);
    elist[p] = s;
}

// ---------------- W prep ----------------
__global__ void k_prepW(const float* __restrict__ W, uint2* __restrict__ whi,
                        uint2* __restrict__ wlo) {
    int id = blockIdx.x * blockDim.x + threadIdx.x;
    int katom = id >> 9, rest = id & 511;
    int natom = rest >> 5, lane = rest & 31;
    int g = lane >> 2, tig = lane & 3;
    int n = natom * 8 + g;
    int k0 = katom * 16 + 2 * tig;
    uint32_t h0, l0, h1, l1;
    cvt_hilo(W[(k0) * 128 + n], W[(k0 + 1) * 128 + n], h0, l0);
    cvt_hilo(W[(k0 + 8) * 128 + n], W[(k0 + 9) * 128 + n], h1, l1);
    whi[id] = make_uint2(h0, h1);
    wlo[id] = make_uint2(l0, l1);
}

// ---- projection ----
__global__ __launch_bounds__(256, 2) void k_proj_mma(
    const float* __restrict__ X, const uint2* __restrict__ whi,
    const uint2* __restrict__ wlo, const float* __restrict__ ns,
    float* __restrict__ Hout, int nrows)
{
    __shared__ uint2 s_wh[4096];
    __shared__ uint2 s_wl[4096];
    const int tid = threadIdx.x, wid = tid >> 5, lane = tid & 31;
    const int g = lane >> 2, tig = lane & 3;
    const int row0 = blockIdx.x * 128;

    {
        const uint4* sh = (const uint4*)whi;
        const uint4* sl = (const uint4*)wlo;
#pragma unroll
        for (int j = 0; j < 8; j++) {
            ((uint4*)s_wh)[tid + 256 * j] = sh[tid + 256 * j];
            ((uint4*)s_wl)[tid + 256 * j] = sl[tid + 256 * j];
        }
    }
    __syncthreads();

    const int r0 = row0 + wid * 16 + g;
    const int r1 = r0 + 8;
    const bool v0 = (r0 < nrows), v1 = (r1 < nrows);
    const float* p0 = X + (size_t)r0 * 128;
    const float* p1 = X + (size_t)r1 * 128;

    float acc[16][4];
#pragma unroll
    for (int na = 0; na < 16; na++)
#pragma unroll
        for (int q = 0; q < 4; q++) acc[na][q] = 0.f;

    const float2 z2 = make_float2(0.f, 0.f);
#pragma unroll 1
    for (int ka = 0; ka < 8; ka++) {
        uint32_t ah[4], al[4];
        int kk = ka * 16 + 2 * tig;
        float2 x00 = v0 ? *(const float2*)(p0 + kk) : z2;
        float2 x01 = v0 ? *(const float2*)(p0 + kk + 8) : z2;
        float2 x10 = v1 ? *(const float2*)(p1 + kk) : z2;
        float2 x11 = v1 ? *(const float2*)(p1 + kk + 8) : z2;
        cvt_hilo(x00.x, x00.y, ah[0], al[0]);
        cvt_hilo(x10.x, x10.y, ah[1], al[1]);
        cvt_hilo(x01.x, x01.y, ah[2], al[2]);
        cvt_hilo(x11.x, x11.y, ah[3], al[3]);
#pragma unroll
        for (int na = 0; na < 16; na++) {
            uint2 bh = s_wh[(ka * 16 + na) * 32 + lane];
            uint2 bl = s_wl[(ka * 16 + na) * 32 + lane];
            mma16816(acc[na], ah, bh.x, bh.y);
            mma16816(acc[na], al, bh.x, bh.y);
            mma16816(acc[na], ah, bl.x, bl.y);
        }
    }

    float s0 = v0 ? ns[r0] : 0.f;
    float s1 = v1 ? ns[r1] : 0.f;
#pragma unroll
    for (int na = 0; na < 16; na++) {
        int col = na * 8 + 2 * tig;
        if (v0) *(float2*)(Hout + (size_t)r0 * 128 + col) =
            make_float2(acc[na][0] * s0, acc[na][1] * s0);
        if (v1) *(float2*)(Hout + (size_t)r1 * 128 + col) =
            make_float2(acc[na][2] * s1, acc[na][3] * s1);
    }
}

// ---- fused aggregate + bias + leakyrelu + fragment pack (round-6 proven) ----
__device__ __forceinline__ float4 gatherRow(const float* __restrict__ H,
                                            const int* __restrict__ el,
                                            int o, int c, int lane) {
    float4 acc = make_float4(0.f, 0.f, 0.f, 0.f);
    for (int i = o; i < o + c; i++) {
        int s = __ldg(&el[i]);
        float4 v = *(const float4*)(H + (size_t)s * 128 + lane * 4);
        acc.x += v.x; acc.y += v.y; acc.z += v.z; acc.w += v.w;
    }
    return acc;
}

__global__ __launch_bounds__(512) void k_aggpack(
    const float* __restrict__ bsc, const float* __restrict__ bin,
    const float* __restrict__ bni, const float* __restrict__ bii,
    uint2* __restrict__ bth, uint2* __restrict__ btl)
{
    __shared__ float s[16][128];
    const int t = blockIdx.x;
    const int wid = threadIdx.x >> 5, lane = threadIdx.x & 31;

    float4 val;
    float b0 = 0.f, b1 = 0.f, b2 = 0.f, b3 = 0.f;
    if (t < 3125) {
        int d = t * 16 + wid;
        float4 a = gatherRow(g_hsc, g_elist, g_off[OB_SC + d], g_cnt[OFF_ND_SC + d], lane);
        float nd = g_deg[OFF_ND_SC + d];
        val = make_float4(a.x * nd, a.y * nd, a.z * nd, a.w * nd);
        b0 = __ldg(&bsc[lane * 4]); b1 = __ldg(&bsc[lane * 4 + 1]);
        b2 = __ldg(&bsc[lane * 4 + 2]); b3 = __ldg(&bsc[lane * 4 + 3]);
    } else if (t < 6250) {
        int d = (t - 3125) * 16 + wid;
        float4 a = gatherRow(g_hin, g_elist, g_off[OB_IN + d], g_cnt[OFF_ND_IN + d], lane);
        float nd = g_deg[OFF_ND_IN + d];
        val = make_float4(a.x * nd, a.y * nd, a.z * nd, a.w * nd);
        b0 = __ldg(&bin[lane * 4]); b1 = __ldg(&bin[lane * 4 + 1]);
        b2 = __ldg(&bin[lane * 4 + 2]); b3 = __ldg(&bin[lane * 4 + 3]);
    } else {
        int d = (t - 6250) * 16 + wid;
        float4 a = gatherRow(g_hni, g_elist, g_off[OB_NI + d], g_cnt[OFF_ND_NI + d], lane);
        float n1 = g_deg[OFF_ND_NI + d];
        float4 c = gatherRow(g_hii, g_elist, g_off[OB_II + d], g_cnt[OFF_ND_II + d], lane);
        float n2 = g_deg[OFF_ND_II + d];
        val = make_float4(a.x * n1 + c.x * n2, a.y * n1 + c.y * n2,
                          a.z * n1 + c.z * n2, a.w * n1 + c.w * n2);
        b0 = __ldg(&bni[lane * 4]) + __ldg(&bii[lane * 4]);
        b1 = __ldg(&bni[lane * 4 + 1]) + __ldg(&bii[lane * 4 + 1]);
        b2 = __ldg(&bni[lane * 4 + 2]) + __ldg(&bii[lane * 4 + 2]);
        b3 = __ldg(&bni[lane * 4 + 3]) + __ldg(&bii[lane * 4 + 3]);
    }
    val.x += b0; val.y += b1; val.z += b2; val.w += b3;
    val.x = (val.x >= 0.f) ? val.x : 0.01f * val.x;
    val.y = (val.y >= 0.f) ? val.y : 0.01f * val.y;
    val.z = (val.z >= 0.f) ? val.z : 0.01f * val.z;
    val.w = (val.w >= 0.f) ? val.w : 0.01f * val.w;
    *(float4*)&s[wid][lane * 4] = val;
    __syncthreads();

    if (threadIdx.x < 128) {
        int h = threadIdx.x;
#pragma unroll
        for (int j = 0; j < 4; j++) {
            int id = h + 128 * j;
            int lane2 = id & 31;
            int natom = id >> 5;
            int gg = lane2 >> 2, tig = lane2 & 3;
            int n = natom * 8 + gg;
            uint32_t h0, l0, h1, l1;
            cvt_hilo(s[2 * tig][n], s[2 * tig + 1][n], h0, l0);
            cvt_hilo(s[2 * tig + 8][n], s[2 * tig + 9][n], h1, l1);
            size_t o = (size_t)t * 512 + id;
            bth[o] = make_uint2(h0, h1);
            btl[o] = make_uint2(l0, l1);
        }
    }
}

__global__ void k_init_out(float* __restrict__ out, const float* __restrict__ btot) {
    int i = blockIdx.x * blockDim.x + threadIdx.x;
    if (i < ODIM * HDIM) out[i] = btot[i >> 7];
}

// ---- final GEMM ----
__global__ __launch_bounds__(256, 2) void k_gemm_mma(const float* __restrict__ Wt,
                                                     const uint2* __restrict__ bth,
                                                     const uint2* __restrict__ btl,
                                                     float* __restrict__ out) {
    __shared__ uint2 s_bh[4096];
    __shared__ uint2 s_bl[4096];
    const int tid = threadIdx.x, wid = tid >> 5, lane = tid & 31;
    const int g = lane >> 2, tig = lane & 3;
    const int chunk = blockIdx.x, mblk = blockIdx.y;

    const int r0 = mblk * 128 + wid * 16 + g;
    const int r1 = r0 + 8;
    const float* p0 = Wt + (size_t)r0 * NTOT;
    const float* p1 = Wt + (size_t)r1 * NTOT;

    float acc[16][4];
#pragma unroll
    for (int na = 0; na < 16; na++)
#pragma unroll
        for (int q = 0; q < 4; q++) acc[na][q] = 0.f;

    for (int sit = 0; sit < KT_PER_CHUNK / 8; sit++) {
        int tile0 = chunk * KT_PER_CHUNK + sit * 8;
        __syncthreads();
        {
            const uint4* sh = (const uint4*)(bth + (size_t)tile0 * 512);
            const uint4* sl = (const uint4*)(btl + (size_t)tile0 * 512);
#pragma unroll
            for (int j = 0; j < 8; j++) {
                ((uint4*)s_bh)[tid + 256 * j] = sh[tid + 256 * j];
                ((uint4*)s_bl)[tid + 256 * j] = sl[tid + 256 * j];
            }
        }
        __syncthreads();
        if (tile0 >= NTILE_VALID) continue;
#pragma unroll 1
        for (int kt = 0; kt < 8; kt++) {
            int ktg = tile0 + kt;
            if (ktg >= NTILE_VALID) break;
            uint32_t ah[4], al[4];
            size_t kk = (size_t)ktg * 16 + 2 * tig;
            float2 x00 = *(const float2*)(p0 + kk);
            float2 x01 = *(const float2*)(p0 + kk + 8);
            float2 x10 = *(const float2*)(p1 + kk);
            float2 x11 = *(const float2*)(p1 + kk + 8);
            cvt_hilo(x00.x, x00.y, ah[0], al[0]);
            cvt_hilo(x10.x, x10.y, ah[1], al[1]);
            cvt_hilo(x01.x, x01.y, ah[2], al[2]);
            cvt_hilo(x11.x, x11.y, ah[3], al[3]);
#pragma unroll
            for (int na = 0; na < 16; na++) {
                uint2 bh = s_bh[(kt * 16 + na) * 32 + lane];
                uint2 bl = s_bl[(kt * 16 + na) * 32 + lane];
                mma16816(acc[na], ah, bh.x, bh.y);
                mma16816(acc[na], al, bh.x, bh.y);
                mma16816(acc[na], ah, bl.x, bl.y);
            }
        }
    }

#pragma unroll
    for (int na = 0; na < 16; na++) {
        int col = na * 8 + 2 * tig;
        float* d0 = out + (size_t)r0 * 128 + col;
        float* d1 = out + (size_t)r1 * 128 + col;
        asm volatile("red.global.add.v2.f32 [%0], {%1, %2};"
                     :: "l"(d0), "f"(acc[na][0]), "f"(acc[na][1]) : "memory");
        asm volatile("red.global.add.v2.f32 [%0], {%1, %2};"
                     :: "l"(d1), "f"(acc[na][2]), "f"(acc[na][3]) : "memory");
    }
}

// ---------------- host ----------------
extern "C" void kernel_launch(void* const* d_in, const int* in_sizes, int n_in,
                              void* d_out, int out_size) {
    (void)in_sizes; (void)n_in; (void)out_size;
    const float* feat_svc  = (const float*)d_in[0];
    const float* feat_inst = (const float*)d_in[1];
    const float* feat_node = (const float*)d_in[2];
    const int* svc_src = (const int*)d_in[3];
    const int* svc_dst = (const int*)d_in[4];
    const int* in_src  = (const int*)d_in[5];
    const int* in_dst  = (const int*)d_in[6];
    const int* ni_src  = (const int*)d_in[7];
    const int* ni_dst  = (const int*)d_in[8];
    const int* ii_src  = (const int*)d_in[9];
    const int* ii_dst  = (const int*)d_in[10];
    const float* W_sc = (const float*)d_in[11];
    const float* b_sc = (const float*)d_in[12];
    const float* W_in = (const float*)d_in[13];
    const float* b_in = (const float*)d_in[14];
    const float* W_ni = (const float*)d_in[15];
    const float* b_ni = (const float*)d_in[16];
    const float* W_ii = (const float*)d_in[17];
    const float* b_ii = (const float*)d_in[18];
    const float* W_tot = (const float*)d_in[19];
    const float* b_tot = (const float*)d_in[20];
    float* out = (float*)d_out;

    float *p_hsc, *p_hin, *p_hni, *p_hii, *p_deg;
    int *p_cnt, *p_off, *p_cur, *p_el, *p_bsum;
    uint2 *p_bth, *p_btl, *p_wfr;
    cudaGetSymbolAddress((void**)&p_hsc, g_hsc);
    cudaGetSymbolAddress((void**)&p_hin, g_hin);
    cudaGetSymbolAddress((void**)&p_hni, g_hni);
    cudaGetSymbolAddress((void**)&p_hii, g_hii);
    cudaGetSymbolAddress((void**)&p_deg, g_deg);
    cudaGetSymbolAddress((void**)&p_cnt, g_cnt);
    cudaGetSymbolAddress((void**)&p_off, g_off);
    cudaGetSymbolAddress((void**)&p_cur, g_cur);
    cudaGetSymbolAddress((void**)&p_el,  g_elist);
    cudaGetSymbolAddress((void**)&p_bsum, g_bsum);
    cudaGetSymbolAddress((void**)&p_bth, g_bth);
    cudaGetSymbolAddress((void**)&p_btl, g_btl);
    cudaGetSymbolAddress((void**)&p_wfr, g_wfr);

    static cudaStream_t s1 = nullptr, s2 = nullptr;
    static cudaEvent_t evRoot = nullptr, evCount = nullptr, evPrep = nullptr, evFill = nullptr;
    if (s1 == nullptr) {
        cudaStreamCreateWithFlags(&s1, cudaStreamNonBlocking);
        cudaStreamCreateWithFlags(&s2, cudaStreamNonBlocking);
        cudaEventCreateWithFlags(&evRoot, cudaEventDisableTiming);
        cudaEventCreateWithFlags(&evCount, cudaEventDisableTiming);
        cudaEventCreateWithFlags(&evPrep, cudaEventDisableTiming);
        cudaEventCreateWithFlags(&evFill, cudaEventDisableTiming);
    }

    cudaEventRecord(evRoot, 0);

    // s2 branch: W fragment prep + output init
    cudaStreamWaitEvent(s2, evRoot, 0);
    k_prepW<<<16, 256, 0, s2>>>(W_sc, p_wfr + 0 * 8192, p_wfr + 0 * 8192 + 4096);
    k_prepW<<<16, 256, 0, s2>>>(W_in, p_wfr + 1 * 8192, p_wfr + 1 * 8192 + 4096);
    k_prepW<<<16, 256, 0, s2>>>(W_ni, p_wfr + 2 * 8192, p_wfr + 2 * 8192 + 4096);
    k_prepW<<<16, 256, 0, s2>>>(W_ii, p_wfr + 3 * 8192, p_wfr + 3 * 8192 + 4096);
    k_init_out<<<(ODIM * HDIM + 255) / 256, 256, 0, s2>>>(out, b_tot);
    cudaEventRecord(evPrep, s2);

    // default: counts + norms
    k_zeroi<<<(600000 + 255) / 256, 256>>>(p_cnt, 600000);
    k_count<<<(2800000 + 255) / 256, 256>>>(svc_src, svc_dst, in_src, in_dst,
                                            ni_src, ni_dst, ii_src, ii_dst, p_cnt);
    cudaEventRecord(evCount, 0);
    k_norm<<<(600000 + 255) / 256, 256>>>(p_cnt, p_deg, 600000);

    // s1 branch: CSR build
    cudaStreamWaitEvent(s1, evCount, 0);
    k_scanA<<<SCAN_BLKS, 1024, 0, s1>>>(p_cnt, p_off, p_bsum);
    k_scanB<<<1, 512, 0, s1>>>(p_bsum);
    k_scanC<<<SCAN_BLKS, 1024, 0, s1>>>(p_off, p_cur, p_bsum);
    k_fill<<<(E_TOT + 255) / 256, 256, 0, s1>>>(svc_src, svc_dst, in_src, in_dst,
                                                ni_src, ni_dst, ii_src, ii_dst, p_cur, p_el);
    cudaEventRecord(evFill, s1);

    // default: projections (need norms + W fragments)
    cudaStreamWaitEvent(0, evPrep, 0);
    k_proj_mma<<<(N_SVC  + 127) / 128, 256>>>(feat_svc,  p_wfr + 0 * 8192, p_wfr + 0 * 8192 + 4096, p_deg + OFF_NS_SC, p_hsc, N_SVC);
    k_proj_mma<<<(N_INST + 127) / 128, 256>>>(feat_inst, p_wfr + 1 * 8192, p_wfr + 1 * 8192 + 4096, p_deg + OFF_NS_IN, p_hin, N_INST);
    k_proj_mma<<<(N_NODE + 127) / 128, 256>>>(feat_node, p_wfr + 2 * 8192, p_wfr + 2 * 8192 + 4096, p_deg + OFF_NS_NI, p_hni, N_NODE);
    k_proj_mma<<<(N_INST + 127) / 128, 256>>>(feat_inst, p_wfr + 3 * 8192, p_wfr + 3 * 8192 + 4096, p_deg + OFF_NS_II, p_hii, N_INST);

    // join CSR branch, then aggregate + pack, then GEMM
    cudaStreamWaitEvent(0, evFill, 0);
    k_aggpack<<<NTILE_VALID, 512>>>(b_sc, b_in, b_ni, b_ii, p_bth, p_btl);

    dim3 gg(GCHUNK, 2);
    k_gemm_mma<<<gg, 256>>>(W_tot, p_bth, p_btl, out);
}